// round 14
// baseline (speedup 1.0000x reference)
#include <cuda_runtime.h>
#include <cuda_fp16.h>

// EdgeClassification: logits[e] = emb[src]@Wsrc@Wcls + emb[dst]@Wdst@Wcls + (b_fuse@Wcls + b_cls)
// prep: fold weights, 8-lane-split dots + shfl reduce.
// project: all nodes -> 21-class tables; 2 nodes per compute thread so the
//          broadcast M-row smem loads amortize (smem wavefronts halved).
// edge: warp-cooperative fp16 gathers (6x8B lanes/edge), MLP-16 batched, smem-staged output.

#define D 128
#define NC 21
#define MP 24          // padded M row in project smem
#define MAXN 50000
#define EPB 256

typedef unsigned long long ull;

__device__ float g_Msrc[D * NC];
__device__ float g_Mdst[D * NC];
__device__ float g_bprime[NC];
// fp16 projection tables: row = 32 halves = 64B (only first 24 halves = 48B ever read)
__device__ __align__(128) uint4 g_Psh[MAXN * 4];
__device__ __align__(128) uint4 g_Pdh[MAXN * 4];

__device__ __forceinline__ void ffma2(ull& acc, ull a, ull b) {
    asm("fma.rn.f32x2 %0, %1, %2, %0;" : "+l"(acc) : "l"(a), "l"(b));
}
__device__ __forceinline__ ull pack2(float lo, float hi) {
    ull r; asm("mov.b64 %0, {%1, %2};" : "=l"(r) : "f"(lo), "f"(hi)); return r;
}
__device__ __forceinline__ void unpack2(ull v, float& lo, float& hi) {
    asm("mov.b64 {%0, %1}, %2;" : "=f"(lo), "=f"(hi) : "l"(v));
}

// ---------------------------------------------------------------------------
// Kernel A: fold weights. Each output's 128-dot split across 8 consecutive
// lanes (q = t&7, 16 j's each), reduced with 3 shfl_xor. 43K threads.
// Outputs 0..5375: M tables. Outputs 5376..5396: bias b'.
// ---------------------------------------------------------------------------
__global__ void __launch_bounds__(256) prep_kernel(
    const float* __restrict__ Wsrc, const float* __restrict__ Wdst,
    const float* __restrict__ bfuse, const float* __restrict__ Wcls,
    const float* __restrict__ bcls)
{
    const int t = blockIdx.x * 256 + threadIdx.x;
    const int o = t >> 3;            // output id
    const int q = t & 7;             // j-eighth
    if (o >= 2 * D * NC + NC) return;

    float a0 = 0.f, a1 = 0.f;
    if (o < 2 * D * NC) {
        const int table = o / (D * NC);
        const int rem = o - table * (D * NC);
        const int k = rem / NC, c = rem - k * NC;
        const float* __restrict__ Wf = (table ? Wdst : Wsrc) + (size_t)k * D + q * 16;
        const float* __restrict__ Wc = Wcls + q * 16 * NC + c;
        #pragma unroll
        for (int jj = 0; jj < 16; jj += 2) {
            a0 = fmaf(Wf[jj],     Wc[jj * NC],       a0);
            a1 = fmaf(Wf[jj + 1], Wc[(jj + 1) * NC], a1);
        }
        a0 += a1;
        a0 += __shfl_xor_sync(0xffffffffu, a0, 1);
        a0 += __shfl_xor_sync(0xffffffffu, a0, 2);
        a0 += __shfl_xor_sync(0xffffffffu, a0, 4);
        if (q == 0)
            (table ? g_Mdst : g_Msrc)[k * NC + c] = a0;
    } else {
        const int c = o - 2 * D * NC;
        const float* __restrict__ Wc = Wcls + q * 16 * NC + c;
        const float* __restrict__ bf = bfuse + q * 16;
        #pragma unroll
        for (int jj = 0; jj < 16; jj += 2) {
            a0 = fmaf(bf[jj],     Wc[jj * NC],       a0);
            a1 = fmaf(bf[jj + 1], Wc[(jj + 1) * NC], a1);
        }
        a0 += a1;
        a0 += __shfl_xor_sync(0xffffffffu, a0, 1);
        a0 += __shfl_xor_sync(0xffffffffu, a0, 2);
        a0 += __shfl_xor_sync(0xffffffffu, a0, 4);
        if (q == 0)
            g_bprime[c] = bcls[c] + a0;
    }
}

// ---------------------------------------------------------------------------
// Kernel B: project all nodes through both folded matrices, one pass.
// 128 threads stage 128 node-rows; threads 0..63 each COMPUTE 2 nodes
// (rows tid and tid+64), so each broadcast M-row smem load feeds 2 nodes:
// smem wavefronts per block per k drop 84 -> 44. f32x2 packed FMAs; fp16 out.
// ---------------------------------------------------------------------------
__global__ void __launch_bounds__(128) project_kernel(
    const float* __restrict__ emb, int N)
{
    __shared__ float sMs[D * MP];     // 12 KB
    __shared__ float sMd[D * MP];     // 12 KB
    __shared__ float sb[NC];
    __shared__ float sE[128 * 33];    // 16.9 KB

    const int tid = threadIdx.x;
    for (int i = tid; i < D * NC; i += 128) {
        int k = i / NC, c = i - k * NC;
        sMs[k * MP + c] = g_Msrc[i];
        sMd[k * MP + c] = g_Mdst[i];
    }
    if (tid < NC) sb[tid] = g_bprime[tid];

    const int n0 = blockIdx.x * 128;
    // two nodes per compute thread: rows tid and tid+64 (tid < 64)
    ull a1s[10], a1d[10], a2s[10], a2d[10];
    float a1s20, a1d20, a2s20, a2d20;
    bool inited = false;

    for (int kc = 0; kc < D; kc += 32) {
        __syncthreads();   // first iter: sM/sb visible; later: prior reads done
        if (!inited) {
            inited = true;
            #pragma unroll
            for (int q = 0; q < 10; ++q) {
                ull b2 = pack2(sb[2 * q], sb[2 * q + 1]);
                a1s[q] = b2; a2s[q] = b2;
                a1d[q] = 0ULL; a2d[q] = 0ULL;
            }
            a1s20 = sb[20]; a2s20 = sb[20];
            a1d20 = 0.f;    a2d20 = 0.f;
        }
        #pragma unroll
        for (int it = 0; it < 32; ++it) {
            int i = tid + it * 128;
            int nl = i >> 5, k = i & 31;
            int n = n0 + nl;
            sE[nl * 33 + k] = (n < N) ? emb[(size_t)n * D + kc + k] : 0.f;
        }
        __syncthreads();
        if (tid < 64) {
            #pragma unroll 4
            for (int k = 0; k < 32; ++k) {
                float v1 = sE[tid * 33 + k];
                float v2 = sE[(tid + 64) * 33 + k];
                ull v1x = pack2(v1, v1);
                ull v2x = pack2(v2, v2);
                const float* __restrict__ mrs = &sMs[(kc + k) * MP];
                const float* __restrict__ mrd = &sMd[(kc + k) * MP];
                #pragma unroll
                for (int q = 0; q < 10; ++q) {
                    ull ms = *reinterpret_cast<const ull*>(mrs + 2 * q);
                    ull md = *reinterpret_cast<const ull*>(mrd + 2 * q);
                    ffma2(a1s[q], v1x, ms);
                    ffma2(a2s[q], v2x, ms);
                    ffma2(a1d[q], v1x, md);
                    ffma2(a2d[q], v2x, md);
                }
                float m20s = mrs[20], m20d = mrd[20];
                a1s20 = fmaf(v1, m20s, a1s20);
                a2s20 = fmaf(v2, m20s, a2s20);
                a1d20 = fmaf(v1, m20d, a1d20);
                a2d20 = fmaf(v2, m20d, a2d20);
            }
        }
    }

    if (tid >= 64) return;
    #pragma unroll
    for (int half = 0; half < 2; ++half) {
        const int n = n0 + tid + half * 64;
        if (n >= N) continue;
        const ull* s2 = half ? a2s : a1s;
        const ull* d2 = half ? a2d : a1d;
        float s20 = half ? a2s20 : a1s20;
        float d20 = half ? a2d20 : a1d20;

        float os[22], od[22];
        #pragma unroll
        for (int q = 0; q < 10; ++q) {
            unpack2(s2[q], os[2 * q], os[2 * q + 1]);
            unpack2(d2[q], od[2 * q], od[2 * q + 1]);
        }
        os[20] = s20; od[20] = d20;
        os[21] = 0.f; od[21] = 0.f;

        uint4 ws[3], wd[3];
        __half2* hs = reinterpret_cast<__half2*>(ws);
        __half2* hd = reinterpret_cast<__half2*>(wd);
        #pragma unroll
        for (int q = 0; q < 11; ++q) {
            hs[q] = __floats2half2_rn(os[2 * q], os[2 * q + 1]);
            hd[q] = __floats2half2_rn(od[2 * q], od[2 * q + 1]);
        }
        hs[11] = __floats2half2_rn(0.f, 0.f);
        hd[11] = __floats2half2_rn(0.f, 0.f);

        uint4* Ps = g_Psh + (size_t)n * 4;
        uint4* Pd = g_Pdh + (size_t)n * 4;
        #pragma unroll
        for (int q = 0; q < 3; ++q) { Ps[q] = ws[q]; Pd[q] = wd[q]; }
    }
}

// ---------------------------------------------------------------------------
// Kernel C: warp-cooperative fp16 gather. 8-lane groups per edge, lanes j<=5
// each load 8B (4 halves = classes 4j..4j+3); 48B of the 64B row touched
// (2 sectors). Fast path issues all 8 iterations' gathers up front
// (16 outstanding LDG.64/thread). Adds in fp32, smem-staged coalesced output.
// ---------------------------------------------------------------------------
__global__ void __launch_bounds__(EPB) edge_kernel(
    const int* __restrict__ ei32, float* __restrict__ out, int E)
{
    __shared__ float tile[EPB * NC];   // 21504
    __shared__ int   sidx[EPB * 2];    // interleaved (src,dst) pairs

    // dtype sniff: int64 => all high words zero (indices < 50000)
    const bool is64 = ((ei32[1] | ei32[3] | ei32[5] | ei32[7]) == 0);

    const int tid = threadIdx.x;
    const long long base = (long long)blockIdx.x * EPB;
    const int valid = (int)min((long long)EPB, (long long)E - base);

    if (is64) {
        const long long* ei = reinterpret_cast<const long long*>(ei32);
        for (int i = tid; i < valid; i += EPB) {
            sidx[2 * i]     = (int)ei[base + i];
            sidx[2 * i + 1] = (int)ei[(long long)E + base + i];
        }
    } else {
        for (int i = tid; i < valid; i += EPB) {
            sidx[2 * i]     = ei32[base + i];
            sidx[2 * i + 1] = ei32[(long long)E + base + i];
        }
    }
    __syncthreads();

    const int j  = tid & 7;
    const int eg = tid >> 3;
    const int c0 = 4 * j;
    const uint2* __restrict__ Ps2 = reinterpret_cast<const uint2*>(g_Psh);
    const uint2* __restrict__ Pd2 = reinterpret_cast<const uint2*>(g_Pdh);

    if (c0 <= 20) {
        if (valid == EPB) {
            // fast path: all 8 iterations' gathers issued before any use (MLP=16)
            int2 p[8]; uint2 A[8], B[8];
            #pragma unroll
            for (int it = 0; it < 8; ++it) {
                int el = eg + 32 * it;
                p[it] = *reinterpret_cast<const int2*>(&sidx[2 * el]);
            }
            #pragma unroll
            for (int it = 0; it < 8; ++it) {
                A[it] = Ps2[(size_t)p[it].x * 8 + j];
                B[it] = Pd2[(size_t)p[it].y * 8 + j];
            }
            #pragma unroll
            for (int it = 0; it < 8; ++it) {
                int el = eg + 32 * it;
                const __half2* ah = reinterpret_cast<const __half2*>(&A[it]);
                const __half2* bh = reinterpret_cast<const __half2*>(&B[it]);
                float2 fa0 = __half22float2(ah[0]), fb0 = __half22float2(bh[0]);
                float* tp = &tile[el * NC + c0];
                if (c0 < 20) {
                    float2 fa1 = __half22float2(ah[1]), fb1 = __half22float2(bh[1]);
                    tp[0] = fa0.x + fb0.x; tp[1] = fa0.y + fb0.y;
                    tp[2] = fa1.x + fb1.x; tp[3] = fa1.y + fb1.y;
                } else {
                    tp[0] = fa0.x + fb0.x;
                }
            }
        } else {
            for (int el = eg; el < valid; el += 32) {
                int s = sidx[2 * el], d = sidx[2 * el + 1];
                uint2 A = Ps2[(size_t)s * 8 + j];
                uint2 B = Pd2[(size_t)d * 8 + j];
                const __half2* ah = reinterpret_cast<const __half2*>(&A);
                const __half2* bh = reinterpret_cast<const __half2*>(&B);
                float2 fa0 = __half22float2(ah[0]), fb0 = __half22float2(bh[0]);
                float* tp = &tile[el * NC + c0];
                if (c0 < 20) {
                    float2 fa1 = __half22float2(ah[1]), fb1 = __half22float2(bh[1]);
                    tp[0] = fa0.x + fb0.x; tp[1] = fa0.y + fb0.y;
                    tp[2] = fa1.x + fb1.x; tp[3] = fa1.y + fb1.y;
                } else {
                    tp[0] = fa0.x + fb0.x;
                }
            }
        }
    }
    __syncthreads();

    float* outp = out + base * NC;
    if (valid == EPB) {
        // 1344 float4 = 5*EPB + 64: compile-time unrolled
        float4* o4 = reinterpret_cast<float4*>(outp);
        const float4* t4 = reinterpret_cast<const float4*>(tile);
        #pragma unroll
        for (int it = 0; it < 5; ++it)
            o4[tid + it * EPB] = t4[tid + it * EPB];
        if (tid < 64)
            o4[tid + 5 * EPB] = t4[tid + 5 * EPB];
    } else {
        const int total = valid * NC;
        for (int i = tid; i < total; i += EPB)
            outp[i] = tile[i];
    }
}

// ---------------------------------------------------------------------------
extern "C" void kernel_launch(void* const* d_in, const int* in_sizes, int n_in,
                              void* d_out, int out_size)
{
    const float* emb   = (const float*)d_in[0];
    const int*   ei    = (const int*)  d_in[1];
    const float* Wsrc  = (const float*)d_in[2];
    const float* Wdst  = (const float*)d_in[3];
    const float* bfuse = (const float*)d_in[4];
    const float* Wcls  = (const float*)d_in[5];
    const float* bcls  = (const float*)d_in[6];
    float* out = (float*)d_out;

    int N = in_sizes[0] / D;
    if (N > MAXN) N = MAXN;
    int E = in_sizes[1] / 2;

    const int prep_threads = 8 * (2 * D * NC + NC);
    prep_kernel<<<(prep_threads + 255) / 256, 256>>>(Wsrc, Wdst, bfuse, Wcls, bcls);

    project_kernel<<<(N + 127) / 128, 128>>>(emb, N);

    edge_kernel<<<(E + EPB - 1) / EPB, EPB>>>(ei, out, E);
}

// round 15
// speedup vs baseline: 1.3304x; 1.3304x over previous
#include <cuda_runtime.h>
#include <cuda_fp16.h>

// EdgeClassification: logits[e] = emb[src]@Wsrc@Wcls + emb[dst]@Wdst@Wcls + (b_fuse@Wcls + b_cls)
// prep: fold weights, 8-lane-split dots + shfl reduce.
// project: all nodes -> 21-class tables (f32x2 FMA), one node/thread (R13 version).
// edge: warp-cooperative fp16 gathers, 4-lane groups x LDG.128 (lane 3 off),
//       MLP-8 batched, smem-staged coalesced output.

#define D 128
#define NC 21
#define MP 24          // padded M row in project smem
#define MAXN 50000
#define EPB 256

typedef unsigned long long ull;

__device__ float g_Msrc[D * NC];
__device__ float g_Mdst[D * NC];
__device__ float g_bprime[NC];
// fp16 projection tables: row = 32 halves = 64B = 2 sectors (21 used)
__device__ __align__(128) uint4 g_Psh[MAXN * 4];
__device__ __align__(128) uint4 g_Pdh[MAXN * 4];

__device__ __forceinline__ void ffma2(ull& acc, ull a, ull b) {
    asm("fma.rn.f32x2 %0, %1, %2, %0;" : "+l"(acc) : "l"(a), "l"(b));
}
__device__ __forceinline__ ull pack2(float lo, float hi) {
    ull r; asm("mov.b64 %0, {%1, %2};" : "=l"(r) : "f"(lo), "f"(hi)); return r;
}
__device__ __forceinline__ void unpack2(ull v, float& lo, float& hi) {
    asm("mov.b64 {%0, %1}, %2;" : "=f"(lo), "=f"(hi) : "l"(v));
}

// ---------------------------------------------------------------------------
// Kernel A: fold weights. Each output's 128-dot split across 8 consecutive
// lanes (q = t&7, 16 j's each), reduced with 3 shfl_xor. 43K threads.
// ---------------------------------------------------------------------------
__global__ void __launch_bounds__(256) prep_kernel(
    const float* __restrict__ Wsrc, const float* __restrict__ Wdst,
    const float* __restrict__ bfuse, const float* __restrict__ Wcls,
    const float* __restrict__ bcls)
{
    const int t = blockIdx.x * 256 + threadIdx.x;
    const int o = t >> 3;            // output id
    const int q = t & 7;             // j-eighth
    if (o >= 2 * D * NC + NC) return;

    float a0 = 0.f, a1 = 0.f;
    if (o < 2 * D * NC) {
        const int table = o / (D * NC);
        const int rem = o - table * (D * NC);
        const int k = rem / NC, c = rem - k * NC;
        const float* __restrict__ Wf = (table ? Wdst : Wsrc) + (size_t)k * D + q * 16;
        const float* __restrict__ Wc = Wcls + q * 16 * NC + c;
        #pragma unroll
        for (int jj = 0; jj < 16; jj += 2) {
            a0 = fmaf(Wf[jj],     Wc[jj * NC],       a0);
            a1 = fmaf(Wf[jj + 1], Wc[(jj + 1) * NC], a1);
        }
        a0 += a1;
        a0 += __shfl_xor_sync(0xffffffffu, a0, 1);
        a0 += __shfl_xor_sync(0xffffffffu, a0, 2);
        a0 += __shfl_xor_sync(0xffffffffu, a0, 4);
        if (q == 0)
            (table ? g_Mdst : g_Msrc)[k * NC + c] = a0;
    } else {
        const int c = o - 2 * D * NC;
        const float* __restrict__ Wc = Wcls + q * 16 * NC + c;
        const float* __restrict__ bf = bfuse + q * 16;
        #pragma unroll
        for (int jj = 0; jj < 16; jj += 2) {
            a0 = fmaf(bf[jj],     Wc[jj * NC],       a0);
            a1 = fmaf(bf[jj + 1], Wc[(jj + 1) * NC], a1);
        }
        a0 += a1;
        a0 += __shfl_xor_sync(0xffffffffu, a0, 1);
        a0 += __shfl_xor_sync(0xffffffffu, a0, 2);
        a0 += __shfl_xor_sync(0xffffffffu, a0, 4);
        if (q == 0)
            g_bprime[c] = bcls[c] + a0;
    }
}

// ---------------------------------------------------------------------------
// Kernel B: project all nodes through both folded matrices, one pass.
// One node per thread, all 128 threads compute (R13 version — the 2-node
// variant spilled registers and halved issue width; reverted).
// ---------------------------------------------------------------------------
__global__ void __launch_bounds__(128) project_kernel(
    const float* __restrict__ emb, int N)
{
    __shared__ float sMs[D * MP];     // 12 KB
    __shared__ float sMd[D * MP];     // 12 KB
    __shared__ float sb[NC];
    __shared__ float sE[128 * 33];    // 16.9 KB

    const int tid = threadIdx.x;
    for (int i = tid; i < D * NC; i += 128) {
        int k = i / NC, c = i - k * NC;
        sMs[k * MP + c] = g_Msrc[i];
        sMd[k * MP + c] = g_Mdst[i];
    }
    if (tid < NC) sb[tid] = g_bprime[tid];

    const int n0 = blockIdx.x * 128;
    ull as2[10], ad2[10];
    float as20, ad20;
    bool inited = false;

    for (int kc = 0; kc < D; kc += 32) {
        __syncthreads();   // first iter: sM/sb visible; later: prior reads done
        if (!inited) {
            inited = true;
            #pragma unroll
            for (int q = 0; q < 10; ++q) {
                as2[q] = pack2(sb[2 * q], sb[2 * q + 1]);
                ad2[q] = 0ULL;
            }
            as20 = sb[20]; ad20 = 0.f;
        }
        #pragma unroll
        for (int it = 0; it < 32; ++it) {
            int i = tid + it * 128;
            int nl = i >> 5, k = i & 31;
            int n = n0 + nl;
            sE[nl * 33 + k] = (n < N) ? emb[(size_t)n * D + kc + k] : 0.f;
        }
        __syncthreads();
        #pragma unroll 4
        for (int k = 0; k < 32; ++k) {
            float v = sE[tid * 33 + k];
            ull v2 = pack2(v, v);
            const float* __restrict__ mrs = &sMs[(kc + k) * MP];
            const float* __restrict__ mrd = &sMd[(kc + k) * MP];
            #pragma unroll
            for (int q = 0; q < 10; ++q) {
                ull ms = *reinterpret_cast<const ull*>(mrs + 2 * q);
                ull md = *reinterpret_cast<const ull*>(mrd + 2 * q);
                ffma2(as2[q], v2, ms);
                ffma2(ad2[q], v2, md);
            }
            as20 = fmaf(v, mrs[20], as20);
            ad20 = fmaf(v, mrd[20], ad20);
        }
    }

    const int n = n0 + tid;
    if (n >= N) return;
    float os[22], od[22];
    #pragma unroll
    for (int q = 0; q < 10; ++q) {
        unpack2(as2[q], os[2 * q], os[2 * q + 1]);
        unpack2(ad2[q], od[2 * q], od[2 * q + 1]);
    }
    os[20] = as20; od[20] = ad20;
    os[21] = 0.f;  od[21] = 0.f;

    uint4 ws[3], wd[3];
    __half2* hs = reinterpret_cast<__half2*>(ws);
    __half2* hd = reinterpret_cast<__half2*>(wd);
    #pragma unroll
    for (int q = 0; q < 11; ++q) {
        hs[q] = __floats2half2_rn(os[2 * q], os[2 * q + 1]);
        hd[q] = __floats2half2_rn(od[2 * q], od[2 * q + 1]);
    }
    hs[11] = __floats2half2_rn(0.f, 0.f);
    hd[11] = __floats2half2_rn(0.f, 0.f);

    uint4* Ps = g_Psh + (size_t)n * 4;
    uint4* Pd = g_Pdh + (size_t)n * 4;
    #pragma unroll
    for (int q = 0; q < 3; ++q) { Ps[q] = ws[q]; Pd[q] = wd[q]; }
}

// ---------------------------------------------------------------------------
// Kernel C: warp-cooperative fp16 gather, 4-lane groups x LDG.128.
// Lane j in 0..2 loads halves 8j..8j+7 (16B) of src+dst rows; lane 3 would
// load pure padding and is predicated off. Same 2 sectors/row as before but
// half the gather instructions and 8 edges per warp-iter. All 4 iterations'
// loads batched (8 LDG.128 outstanding). Adds in fp32, smem-staged output.
// ---------------------------------------------------------------------------
__global__ void __launch_bounds__(EPB) edge_kernel(
    const int* __restrict__ ei32, float* __restrict__ out, int E)
{
    __shared__ float tile[EPB * NC];   // 21504
    __shared__ int   sidx[EPB * 2];    // interleaved (src,dst) pairs

    // dtype sniff: int64 => all high words zero (indices < 50000)
    const bool is64 = ((ei32[1] | ei32[3] | ei32[5] | ei32[7]) == 0);

    const int tid = threadIdx.x;
    const long long base = (long long)blockIdx.x * EPB;
    const int valid = (int)min((long long)EPB, (long long)E - base);

    if (is64) {
        const long long* ei = reinterpret_cast<const long long*>(ei32);
        for (int i = tid; i < valid; i += EPB) {
            sidx[2 * i]     = (int)ei[base + i];
            sidx[2 * i + 1] = (int)ei[(long long)E + base + i];
        }
    } else {
        for (int i = tid; i < valid; i += EPB) {
            sidx[2 * i]     = ei32[base + i];
            sidx[2 * i + 1] = ei32[(long long)E + base + i];
        }
    }
    __syncthreads();

    const int j  = tid & 3;   // 16B-chunk index within row (lane 3 idle)
    const int eg = tid >> 2;  // edge group: 64 concurrent edges per block-iter
    const uint4* __restrict__ Ps4 = reinterpret_cast<const uint4*>(g_Psh);
    const uint4* __restrict__ Pd4 = reinterpret_cast<const uint4*>(g_Pdh);

    if (j < 3) {
        if (valid == EPB) {
            // fast path: all 4 iterations' gathers issued before any use
            int2 p[4]; uint4 A[4], B[4];
            #pragma unroll
            for (int it = 0; it < 4; ++it) {
                int el = eg + 64 * it;
                p[it] = *reinterpret_cast<const int2*>(&sidx[2 * el]);
            }
            #pragma unroll
            for (int it = 0; it < 4; ++it) {
                A[it] = Ps4[(size_t)p[it].x * 4 + j];
                B[it] = Pd4[(size_t)p[it].y * 4 + j];
            }
            #pragma unroll
            for (int it = 0; it < 4; ++it) {
                int el = eg + 64 * it;
                const __half2* ah = reinterpret_cast<const __half2*>(&A[it]);
                const __half2* bh = reinterpret_cast<const __half2*>(&B[it]);
                float* tp = &tile[el * NC + 8 * j];
                if (j < 2) {
                    #pragma unroll
                    for (int q = 0; q < 4; ++q) {
                        float2 fa = __half22float2(ah[q]);
                        float2 fb = __half22float2(bh[q]);
                        tp[2 * q]     = fa.x + fb.x;
                        tp[2 * q + 1] = fa.y + fb.y;
                    }
                } else {
                    // j == 2: classes 16..20 (5 values)
                    #pragma unroll
                    for (int q = 0; q < 2; ++q) {
                        float2 fa = __half22float2(ah[q]);
                        float2 fb = __half22float2(bh[q]);
                        tp[2 * q]     = fa.x + fb.x;
                        tp[2 * q + 1] = fa.y + fb.y;
                    }
                    float2 fa = __half22float2(ah[2]);
                    float2 fb = __half22float2(bh[2]);
                    tp[4] = fa.x + fb.x;
                }
            }
        } else {
            for (int el = eg; el < valid; el += 64) {
                int s = sidx[2 * el], d = sidx[2 * el + 1];
                uint4 A = Ps4[(size_t)s * 4 + j];
                uint4 B = Pd4[(size_t)d * 4 + j];
                const __half2* ah = reinterpret_cast<const __half2*>(&A);
                const __half2* bh = reinterpret_cast<const __half2*>(&B);
                float* tp = &tile[el * NC + 8 * j];
                if (j < 2) {
                    #pragma unroll
                    for (int q = 0; q < 4; ++q) {
                        float2 fa = __half22float2(ah[q]);
                        float2 fb = __half22float2(bh[q]);
                        tp[2 * q]     = fa.x + fb.x;
                        tp[2 * q + 1] = fa.y + fb.y;
                    }
                } else {
                    #pragma unroll
                    for (int q = 0; q < 2; ++q) {
                        float2 fa = __half22float2(ah[q]);
                        float2 fb = __half22float2(bh[q]);
                        tp[2 * q]     = fa.x + fb.x;
                        tp[2 * q + 1] = fa.y + fb.y;
                    }
                    float2 fa = __half22float2(ah[2]);
                    float2 fb = __half22float2(bh[2]);
                    tp[4] = fa.x + fb.x;
                }
            }
        }
    }
    __syncthreads();

    float* outp = out + base * NC;
    if (valid == EPB) {
        // 1344 float4 = 5*EPB + 64: compile-time unrolled
        float4* o4 = reinterpret_cast<float4*>(outp);
        const float4* t4 = reinterpret_cast<const float4*>(tile);
        #pragma unroll
        for (int it = 0; it < 5; ++it)
            o4[tid + it * EPB] = t4[tid + it * EPB];
        if (tid < 64)
            o4[tid + 5 * EPB] = t4[tid + 5 * EPB];
    } else {
        const int total = valid * NC;
        for (int i = tid; i < total; i += EPB)
            outp[i] = tile[i];
    }
}

// ---------------------------------------------------------------------------
extern "C" void kernel_launch(void* const* d_in, const int* in_sizes, int n_in,
                              void* d_out, int out_size)
{
    const float* emb   = (const float*)d_in[0];
    const int*   ei    = (const int*)  d_in[1];
    const float* Wsrc  = (const float*)d_in[2];
    const float* Wdst  = (const float*)d_in[3];
    const float* bfuse = (const float*)d_in[4];
    const float* Wcls  = (const float*)d_in[5];
    const float* bcls  = (const float*)d_in[6];
    float* out = (float*)d_out;

    int N = in_sizes[0] / D;
    if (N > MAXN) N = MAXN;
    int E = in_sizes[1] / 2;

    const int prep_threads = 8 * (2 * D * NC + NC);
    prep_kernel<<<(prep_threads + 255) / 256, 256>>>(Wsrc, Wdst, bfuse, Wcls, bcls);

    project_kernel<<<(N + 127) / 128, 128>>>(emb, N);

    edge_kernel<<<(E + EPB - 1) / EPB, EPB>>>(ei, out, E);
}

// round 16
// speedup vs baseline: 1.3823x; 1.0390x over previous
#include <cuda_runtime.h>
#include <cuda_fp16.h>

// EdgeClassification: logits[e] = emb[src]@Wsrc@Wcls + emb[dst]@Wdst@Wcls + (b_fuse@Wcls + b_cls)
// prep: fold weights, 8-lane-split dots + shfl reduce.
// project: all nodes -> 21-class tables; M rows loaded as LDS.128 (ulonglong2)
//          so the kernel is FMA-bound, not LDS-issue bound.
// edge: warp-cooperative fp16 gathers (6x8B lanes/edge), MLP-16 batched (R13 best).

#define D 128
#define NC 21
#define MP 24          // padded M row in project smem (96B, 16B-aligned)
#define MAXN 50000
#define EPB 256

typedef unsigned long long ull;

__device__ float g_Msrc[D * NC];
__device__ float g_Mdst[D * NC];
__device__ float g_bprime[NC];
// fp16 projection tables: row = 32 halves = 64B = 2 sectors (21 used)
__device__ __align__(128) uint4 g_Psh[MAXN * 4];
__device__ __align__(128) uint4 g_Pdh[MAXN * 4];

__device__ __forceinline__ void ffma2(ull& acc, ull a, ull b) {
    asm("fma.rn.f32x2 %0, %1, %2, %0;" : "+l"(acc) : "l"(a), "l"(b));
}
__device__ __forceinline__ ull pack2(float lo, float hi) {
    ull r; asm("mov.b64 %0, {%1, %2};" : "=l"(r) : "f"(lo), "f"(hi)); return r;
}
__device__ __forceinline__ void unpack2(ull v, float& lo, float& hi) {
    asm("mov.b64 {%0, %1}, %2;" : "=f"(lo), "=f"(hi) : "l"(v));
}

// ---------------------------------------------------------------------------
// Kernel A: fold weights. Each output's 128-dot split across 8 consecutive
// lanes (q = t&7, 16 j's each), reduced with 3 shfl_xor. 43K threads.
// ---------------------------------------------------------------------------
__global__ void __launch_bounds__(256) prep_kernel(
    const float* __restrict__ Wsrc, const float* __restrict__ Wdst,
    const float* __restrict__ bfuse, const float* __restrict__ Wcls,
    const float* __restrict__ bcls)
{
    const int t = blockIdx.x * 256 + threadIdx.x;
    const int o = t >> 3;            // output id
    const int q = t & 7;             // j-eighth
    if (o >= 2 * D * NC + NC) return;

    float a0 = 0.f, a1 = 0.f;
    if (o < 2 * D * NC) {
        const int table = o / (D * NC);
        const int rem = o - table * (D * NC);
        const int k = rem / NC, c = rem - k * NC;
        const float* __restrict__ Wf = (table ? Wdst : Wsrc) + (size_t)k * D + q * 16;
        const float* __restrict__ Wc = Wcls + q * 16 * NC + c;
        #pragma unroll
        for (int jj = 0; jj < 16; jj += 2) {
            a0 = fmaf(Wf[jj],     Wc[jj * NC],       a0);
            a1 = fmaf(Wf[jj + 1], Wc[(jj + 1) * NC], a1);
        }
        a0 += a1;
        a0 += __shfl_xor_sync(0xffffffffu, a0, 1);
        a0 += __shfl_xor_sync(0xffffffffu, a0, 2);
        a0 += __shfl_xor_sync(0xffffffffu, a0, 4);
        if (q == 0)
            (table ? g_Mdst : g_Msrc)[k * NC + c] = a0;
    } else {
        const int c = o - 2 * D * NC;
        const float* __restrict__ Wc = Wcls + q * 16 * NC + c;
        const float* __restrict__ bf = bfuse + q * 16;
        #pragma unroll
        for (int jj = 0; jj < 16; jj += 2) {
            a0 = fmaf(bf[jj],     Wc[jj * NC],       a0);
            a1 = fmaf(bf[jj + 1], Wc[(jj + 1) * NC], a1);
        }
        a0 += a1;
        a0 += __shfl_xor_sync(0xffffffffu, a0, 1);
        a0 += __shfl_xor_sync(0xffffffffu, a0, 2);
        a0 += __shfl_xor_sync(0xffffffffu, a0, 4);
        if (q == 0)
            g_bprime[c] = bcls[c] + a0;
    }
}

// ---------------------------------------------------------------------------
// Kernel B: project all nodes through both folded matrices, one pass.
// One node per thread. M rows read as 5x LDS.128 (ulonglong2) per table
// per k (broadcast, conflict-free) -> 13 LDS vs 22 FFMA2 per k: FMA-bound.
// ---------------------------------------------------------------------------
__global__ void __launch_bounds__(128) project_kernel(
    const float* __restrict__ emb, int N)
{
    __shared__ __align__(16) float sMs[D * MP];   // 12 KB
    __shared__ __align__(16) float sMd[D * MP];   // 12 KB
    __shared__ float sb[NC];
    __shared__ float sE[128 * 33];                // 16.9 KB

    const int tid = threadIdx.x;
    for (int i = tid; i < D * NC; i += 128) {
        int k = i / NC, c = i - k * NC;
        sMs[k * MP + c] = g_Msrc[i];
        sMd[k * MP + c] = g_Mdst[i];
    }
    if (tid < NC) sb[tid] = g_bprime[tid];

    const int n0 = blockIdx.x * 128;
    ull as2[10], ad2[10];
    float as20, ad20;
    bool inited = false;

    for (int kc = 0; kc < D; kc += 32) {
        __syncthreads();   // first iter: sM/sb visible; later: prior reads done
        if (!inited) {
            inited = true;
            #pragma unroll
            for (int q = 0; q < 10; ++q) {
                as2[q] = pack2(sb[2 * q], sb[2 * q + 1]);
                ad2[q] = 0ULL;
            }
            as20 = sb[20]; ad20 = 0.f;
        }
        #pragma unroll
        for (int it = 0; it < 32; ++it) {
            int i = tid + it * 128;
            int nl = i >> 5, k = i & 31;
            int n = n0 + nl;
            sE[nl * 33 + k] = (n < N) ? emb[(size_t)n * D + kc + k] : 0.f;
        }
        __syncthreads();
        #pragma unroll 4
        for (int k = 0; k < 32; ++k) {
            float v = sE[tid * 33 + k];
            ull v2 = pack2(v, v);
            const float* __restrict__ mrs = &sMs[(kc + k) * MP];
            const float* __restrict__ mrd = &sMd[(kc + k) * MP];
            const ulonglong2* __restrict__ mrs4 = reinterpret_cast<const ulonglong2*>(mrs);
            const ulonglong2* __restrict__ mrd4 = reinterpret_cast<const ulonglong2*>(mrd);
            #pragma unroll
            for (int q = 0; q < 5; ++q) {
                ulonglong2 ms = mrs4[q];
                ulonglong2 md = mrd4[q];
                ffma2(as2[2 * q],     v2, ms.x);
                ffma2(as2[2 * q + 1], v2, ms.y);
                ffma2(ad2[2 * q],     v2, md.x);
                ffma2(ad2[2 * q + 1], v2, md.y);
            }
            as20 = fmaf(v, mrs[20], as20);
            ad20 = fmaf(v, mrd[20], ad20);
        }
    }

    const int n = n0 + tid;
    if (n >= N) return;
    float os[22], od[22];
    #pragma unroll
    for (int q = 0; q < 10; ++q) {
        unpack2(as2[q], os[2 * q], os[2 * q + 1]);
        unpack2(ad2[q], od[2 * q], od[2 * q + 1]);
    }
    os[20] = as20; od[20] = ad20;
    os[21] = 0.f;  od[21] = 0.f;

    uint4 ws[3], wd[3];
    __half2* hs = reinterpret_cast<__half2*>(ws);
    __half2* hd = reinterpret_cast<__half2*>(wd);
    #pragma unroll
    for (int q = 0; q < 11; ++q) {
        hs[q] = __floats2half2_rn(os[2 * q], os[2 * q + 1]);
        hd[q] = __floats2half2_rn(od[2 * q], od[2 * q + 1]);
    }
    hs[11] = __floats2half2_rn(0.f, 0.f);
    hd[11] = __floats2half2_rn(0.f, 0.f);

    uint4* Ps = g_Psh + (size_t)n * 4;
    uint4* Pd = g_Pdh + (size_t)n * 4;
    #pragma unroll
    for (int q = 0; q < 3; ++q) { Ps[q] = ws[q]; Pd[q] = wd[q]; }
}

// ---------------------------------------------------------------------------
// Kernel C: warp-cooperative fp16 gather (R13 measured-best). 8-lane groups
// per edge, lanes j<=5 load 8B each (48B of the 64B row = 2 sectors). Fast
// path issues all 8 iterations' gathers up front (16 outstanding LDG.64).
// Adds in fp32, smem-staged coalesced output.
// ---------------------------------------------------------------------------
__global__ void __launch_bounds__(EPB) edge_kernel(
    const int* __restrict__ ei32, float* __restrict__ out, int E)
{
    __shared__ float tile[EPB * NC];   // 21504
    __shared__ int   sidx[EPB * 2];    // interleaved (src,dst) pairs

    // dtype sniff: int64 => all high words zero (indices < 50000)
    const bool is64 = ((ei32[1] | ei32[3] | ei32[5] | ei32[7]) == 0);

    const int tid = threadIdx.x;
    const long long base = (long long)blockIdx.x * EPB;
    const int valid = (int)min((long long)EPB, (long long)E - base);

    if (is64) {
        const long long* ei = reinterpret_cast<const long long*>(ei32);
        for (int i = tid; i < valid; i += EPB) {
            sidx[2 * i]     = (int)ei[base + i];
            sidx[2 * i + 1] = (int)ei[(long long)E + base + i];
        }
    } else {
        for (int i = tid; i < valid; i += EPB) {
            sidx[2 * i]     = ei32[base + i];
            sidx[2 * i + 1] = ei32[(long long)E + base + i];
        }
    }
    __syncthreads();

    const int j  = tid & 7;
    const int eg = tid >> 3;
    const int c0 = 4 * j;
    const uint2* __restrict__ Ps2 = reinterpret_cast<const uint2*>(g_Psh);
    const uint2* __restrict__ Pd2 = reinterpret_cast<const uint2*>(g_Pdh);

    if (c0 <= 20) {
        if (valid == EPB) {
            // fast path: all 8 iterations' gathers issued before any use (MLP=16)
            int2 p[8]; uint2 A[8], B[8];
            #pragma unroll
            for (int it = 0; it < 8; ++it) {
                int el = eg + 32 * it;
                p[it] = *reinterpret_cast<const int2*>(&sidx[2 * el]);
            }
            #pragma unroll
            for (int it = 0; it < 8; ++it) {
                A[it] = Ps2[(size_t)p[it].x * 8 + j];
                B[it] = Pd2[(size_t)p[it].y * 8 + j];
            }
            #pragma unroll
            for (int it = 0; it < 8; ++it) {
                int el = eg + 32 * it;
                const __half2* ah = reinterpret_cast<const __half2*>(&A[it]);
                const __half2* bh = reinterpret_cast<const __half2*>(&B[it]);
                float2 fa0 = __half22float2(ah[0]), fb0 = __half22float2(bh[0]);
                float* tp = &tile[el * NC + c0];
                if (c0 < 20) {
                    float2 fa1 = __half22float2(ah[1]), fb1 = __half22float2(bh[1]);
                    tp[0] = fa0.x + fb0.x; tp[1] = fa0.y + fb0.y;
                    tp[2] = fa1.x + fb1.x; tp[3] = fa1.y + fb1.y;
                } else {
                    tp[0] = fa0.x + fb0.x;
                }
            }
        } else {
            for (int el = eg; el < valid; el += 32) {
                int s = sidx[2 * el], d = sidx[2 * el + 1];
                uint2 A = Ps2[(size_t)s * 8 + j];
                uint2 B = Pd2[(size_t)d * 8 + j];
                const __half2* ah = reinterpret_cast<const __half2*>(&A);
                const __half2* bh = reinterpret_cast<const __half2*>(&B);
                float2 fa0 = __half22float2(ah[0]), fb0 = __half22float2(bh[0]);
                float* tp = &tile[el * NC + c0];
                if (c0 < 20) {
                    float2 fa1 = __half22float2(ah[1]), fb1 = __half22float2(bh[1]);
                    tp[0] = fa0.x + fb0.x; tp[1] = fa0.y + fb0.y;
                    tp[2] = fa1.x + fb1.x; tp[3] = fa1.y + fb1.y;
                } else {
                    tp[0] = fa0.x + fb0.x;
                }
            }
        }
    }
    __syncthreads();

    float* outp = out + base * NC;
    if (valid == EPB) {
        // 1344 float4 = 5*EPB + 64: compile-time unrolled
        float4* o4 = reinterpret_cast<float4*>(outp);
        const float4* t4 = reinterpret_cast<const float4*>(tile);
        #pragma unroll
        for (int it = 0; it < 5; ++it)
            o4[tid + it * EPB] = t4[tid + it * EPB];
        if (tid < 64)
            o4[tid + 5 * EPB] = t4[tid + 5 * EPB];
    } else {
        const int total = valid * NC;
        for (int i = tid; i < total; i += EPB)
            outp[i] = tile[i];
    }
}

// ---------------------------------------------------------------------------
extern "C" void kernel_launch(void* const* d_in, const int* in_sizes, int n_in,
                              void* d_out, int out_size)
{
    const float* emb   = (const float*)d_in[0];
    const int*   ei    = (const int*)  d_in[1];
    const float* Wsrc  = (const float*)d_in[2];
    const float* Wdst  = (const float*)d_in[3];
    const float* bfuse = (const float*)d_in[4];
    const float* Wcls  = (const float*)d_in[5];
    const float* bcls  = (const float*)d_in[6];
    float* out = (float*)d_out;

    int N = in_sizes[0] / D;
    if (N > MAXN) N = MAXN;
    int E = in_sizes[1] / 2;

    const int prep_threads = 8 * (2 * D * NC + NC);
    prep_kernel<<<(prep_threads + 255) / 256, 256>>>(Wsrc, Wdst, bfuse, Wcls, bcls);

    project_kernel<<<(N + 127) / 128, 128>>>(emb, N);

    edge_kernel<<<(E + EPB - 1) / EPB, EPB>>>(ei, out, E);
}

// round 17
// speedup vs baseline: 1.4590x; 1.0555x over previous
#include <cuda_runtime.h>
#include <cuda_fp16.h>

// EdgeClassification: logits[e] = emb[src]@Wsrc@Wcls + emb[dst]@Wdst@Wcls + (b_fuse@Wcls + b_cls)
// prep: fold weights, 8-lane-split dots + shfl reduce.
// project: all nodes -> 21-class fp16 tables; PDL: stages first emb chunk before
//          waiting on prep.
// edge: one-edge-per-lane index loads + shfl distribution to 8-lane gather groups,
//       MLP-16 batched fp16 gathers; PDL: loads indices before waiting on project.

#define D 128
#define NC 21
#define MP 24          // padded M row in project smem (96B, 16B-aligned)
#define MAXN 50000
#define EPB 256

typedef unsigned long long ull;

__device__ float g_Msrc[D * NC];
__device__ float g_Mdst[D * NC];
__device__ float g_bprime[NC];
// fp16 projection tables: row = 32 halves = 64B = 2 sectors (21 used)
__device__ __align__(128) uint4 g_Psh[MAXN * 4];
__device__ __align__(128) uint4 g_Pdh[MAXN * 4];

__device__ __forceinline__ void ffma2(ull& acc, ull a, ull b) {
    asm("fma.rn.f32x2 %0, %1, %2, %0;" : "+l"(acc) : "l"(a), "l"(b));
}
__device__ __forceinline__ ull pack2(float lo, float hi) {
    ull r; asm("mov.b64 %0, {%1, %2};" : "=l"(r) : "f"(lo), "f"(hi)); return r;
}
__device__ __forceinline__ void unpack2(ull v, float& lo, float& hi) {
    asm("mov.b64 {%0, %1}, %2;" : "=f"(lo), "=f"(hi) : "l"(v));
}

// ---------------------------------------------------------------------------
// Kernel A: fold weights. Each output's 128-dot split across 8 consecutive
// lanes (q = t&7, 16 j's each), reduced with 3 shfl_xor. 43K threads.
// ---------------------------------------------------------------------------
__global__ void __launch_bounds__(256) prep_kernel(
    const float* __restrict__ Wsrc, const float* __restrict__ Wdst,
    const float* __restrict__ bfuse, const float* __restrict__ Wcls,
    const float* __restrict__ bcls)
{
    const int t = blockIdx.x * 256 + threadIdx.x;
    const int o = t >> 3;            // output id
    const int q = t & 7;             // j-eighth
    if (o >= 2 * D * NC + NC) return;

    float a0 = 0.f, a1 = 0.f;
    if (o < 2 * D * NC) {
        const int table = o / (D * NC);
        const int rem = o - table * (D * NC);
        const int k = rem / NC, c = rem - k * NC;
        const float* __restrict__ Wf = (table ? Wdst : Wsrc) + (size_t)k * D + q * 16;
        const float* __restrict__ Wc = Wcls + q * 16 * NC + c;
        #pragma unroll
        for (int jj = 0; jj < 16; jj += 2) {
            a0 = fmaf(Wf[jj],     Wc[jj * NC],       a0);
            a1 = fmaf(Wf[jj + 1], Wc[(jj + 1) * NC], a1);
        }
        a0 += a1;
        a0 += __shfl_xor_sync(0xffffffffu, a0, 1);
        a0 += __shfl_xor_sync(0xffffffffu, a0, 2);
        a0 += __shfl_xor_sync(0xffffffffu, a0, 4);
        if (q == 0)
            (table ? g_Mdst : g_Msrc)[k * NC + c] = a0;
    } else {
        const int c = o - 2 * D * NC;
        const float* __restrict__ Wc = Wcls + q * 16 * NC + c;
        const float* __restrict__ bf = bfuse + q * 16;
        #pragma unroll
        for (int jj = 0; jj < 16; jj += 2) {
            a0 = fmaf(bf[jj],     Wc[jj * NC],       a0);
            a1 = fmaf(bf[jj + 1], Wc[(jj + 1) * NC], a1);
        }
        a0 += a1;
        a0 += __shfl_xor_sync(0xffffffffu, a0, 1);
        a0 += __shfl_xor_sync(0xffffffffu, a0, 2);
        a0 += __shfl_xor_sync(0xffffffffu, a0, 4);
        if (q == 0)
            g_bprime[c] = bcls[c] + a0;
    }
}

// ---------------------------------------------------------------------------
// Kernel B: project all nodes through both folded matrices, one pass.
// PDL: first emb chunk staged BEFORE the dependency sync (overlaps prep tail).
// M rows read as 5x LDS.128 per table per k (broadcast, conflict-free).
// ---------------------------------------------------------------------------
__global__ void __launch_bounds__(128) project_kernel(
    const float* __restrict__ emb, int N)
{
    __shared__ __align__(16) float sMs[D * MP];   // 12 KB
    __shared__ __align__(16) float sMd[D * MP];   // 12 KB
    __shared__ float sb[NC];
    __shared__ float sE[128 * 33];                // 16.9 KB

    const int tid = threadIdx.x;
    const int n0 = blockIdx.x * 128;

    // Stage emb chunk 0 (independent of prep output)
    #pragma unroll
    for (int it = 0; it < 32; ++it) {
        int i = tid + it * 128;
        int nl = i >> 5, k = i & 31;
        int n = n0 + nl;
        sE[nl * 33 + k] = (n < N) ? emb[(size_t)n * D + k] : 0.f;
    }

    cudaGridDependencySynchronize();   // wait for prep's M tables

    for (int i = tid; i < D * NC; i += 128) {
        int k = i / NC, c = i - k * NC;
        sMs[k * MP + c] = g_Msrc[i];
        sMd[k * MP + c] = g_Mdst[i];
    }
    if (tid < NC) sb[tid] = g_bprime[tid];
    __syncthreads();   // sE chunk0 + sM + sb visible

    ull as2[10], ad2[10];
    float as20, ad20;
    #pragma unroll
    for (int q = 0; q < 10; ++q) {
        as2[q] = pack2(sb[2 * q], sb[2 * q + 1]);
        ad2[q] = 0ULL;
    }
    as20 = sb[20]; ad20 = 0.f;

    for (int kc = 0; ; kc += 32) {
        #pragma unroll 4
        for (int k = 0; k < 32; ++k) {
            float v = sE[tid * 33 + k];
            ull v2 = pack2(v, v);
            const float* __restrict__ mrs = &sMs[(kc + k) * MP];
            const float* __restrict__ mrd = &sMd[(kc + k) * MP];
            const ulonglong2* __restrict__ mrs4 = reinterpret_cast<const ulonglong2*>(mrs);
            const ulonglong2* __restrict__ mrd4 = reinterpret_cast<const ulonglong2*>(mrd);
            #pragma unroll
            for (int q = 0; q < 5; ++q) {
                ulonglong2 ms = mrs4[q];
                ulonglong2 md = mrd4[q];
                ffma2(as2[2 * q],     v2, ms.x);
                ffma2(as2[2 * q + 1], v2, ms.y);
                ffma2(ad2[2 * q],     v2, md.x);
                ffma2(ad2[2 * q + 1], v2, md.y);
            }
            as20 = fmaf(v, mrs[20], as20);
            ad20 = fmaf(v, mrd[20], ad20);
        }
        if (kc == 96) break;
        __syncthreads();   // done reading sE
        #pragma unroll
        for (int it = 0; it < 32; ++it) {
            int i = tid + it * 128;
            int nl = i >> 5, k = i & 31;
            int n = n0 + nl;
            sE[nl * 33 + k] = (n < N) ? emb[(size_t)n * D + kc + 32 + k] : 0.f;
        }
        __syncthreads();
    }

    const int n = n0 + tid;
    if (n >= N) return;
    float os[22], od[22];
    #pragma unroll
    for (int q = 0; q < 10; ++q) {
        unpack2(as2[q], os[2 * q], os[2 * q + 1]);
        unpack2(ad2[q], od[2 * q], od[2 * q + 1]);
    }
    os[20] = as20; od[20] = ad20;
    os[21] = 0.f;  od[21] = 0.f;

    uint4 ws[3], wd[3];
    __half2* hs = reinterpret_cast<__half2*>(ws);
    __half2* hd = reinterpret_cast<__half2*>(wd);
    #pragma unroll
    for (int q = 0; q < 11; ++q) {
        hs[q] = __floats2half2_rn(os[2 * q], os[2 * q + 1]);
        hd[q] = __floats2half2_rn(od[2 * q], od[2 * q + 1]);
    }
    hs[11] = __floats2half2_rn(0.f, 0.f);
    hd[11] = __floats2half2_rn(0.f, 0.f);

    uint4* Ps = g_Psh + (size_t)n * 4;
    uint4* Pd = g_Pdh + (size_t)n * 4;
    #pragma unroll
    for (int q = 0; q < 3; ++q) { Ps[q] = ws[q]; Pd[q] = wd[q]; }
}

// ---------------------------------------------------------------------------
// Kernel C: one edge per lane index loads (coalesced), shfl-distributed to
// 8-lane gather groups (no smem idx staging, no first barrier). Lanes j<=5
// load 8B each (48B of the 64B row = 2 sectors). Fast path batches all 16
// gathers. PDL: index loads issued before the dependency sync on project.
// ---------------------------------------------------------------------------
__global__ void __launch_bounds__(EPB) edge_kernel(
    const int* __restrict__ ei32, float* __restrict__ out, int E)
{
    __shared__ float tile[EPB * NC];   // 21504

    // dtype sniff: int64 => all high words zero (indices < 50000)
    const bool is64 = ((ei32[1] | ei32[3] | ei32[5] | ei32[7]) == 0);

    const int tid  = threadIdx.x;
    const int lane = tid & 31;
    const int w    = tid >> 5;         // warp 0..7, owns edges 32w..32w+31
    const long long base = (long long)blockIdx.x * EPB;
    const int valid = (int)min((long long)EPB, (long long)E - base);
    const int el0 = 32 * w + lane;     // this lane's owned edge (block-local)

    // Load own edge's (src,dst) — coalesced; independent of project output.
    int s0 = 0, d0 = 0;
    if (el0 < valid) {
        long long e = base + el0;
        if (is64) {
            const long long* ei = reinterpret_cast<const long long*>(ei32);
            s0 = (int)ei[e];
            d0 = (int)ei[(long long)E + e];
        } else {
            s0 = ei32[e];
            d0 = ei32[(long long)E + e];
        }
    }

    const int j  = lane & 7;           // row chunk (8B of fp16)
    const int g  = lane >> 3;          // gather group 0..3
    const int c0 = 4 * j;

    // Distribute: iteration it, group g handles block-local edge 32w + 4it + g.
    int sx[8], dx[8];
    #pragma unroll
    for (int it = 0; it < 8; ++it) {
        int srcl = 4 * it + g;
        sx[it] = __shfl_sync(0xffffffffu, s0, srcl);
        dx[it] = __shfl_sync(0xffffffffu, d0, srcl);
    }

    cudaGridDependencySynchronize();   // tables from project now valid

    const uint2* __restrict__ Ps2 = reinterpret_cast<const uint2*>(g_Psh);
    const uint2* __restrict__ Pd2 = reinterpret_cast<const uint2*>(g_Pdh);

    if (c0 <= 20) {
        if (valid == EPB) {
            uint2 A[8], B[8];
            #pragma unroll
            for (int it = 0; it < 8; ++it) {
                A[it] = Ps2[(size_t)sx[it] * 8 + j];
                B[it] = Pd2[(size_t)dx[it] * 8 + j];
            }
            #pragma unroll
            for (int it = 0; it < 8; ++it) {
                int el = 32 * w + 4 * it + g;
                const __half2* ah = reinterpret_cast<const __half2*>(&A[it]);
                const __half2* bh = reinterpret_cast<const __half2*>(&B[it]);
                float2 fa0 = __half22float2(ah[0]), fb0 = __half22float2(bh[0]);
                float* tp = &tile[el * NC + c0];
                if (c0 < 20) {
                    float2 fa1 = __half22float2(ah[1]), fb1 = __half22float2(bh[1]);
                    tp[0] = fa0.x + fb0.x; tp[1] = fa0.y + fb0.y;
                    tp[2] = fa1.x + fb1.x; tp[3] = fa1.y + fb1.y;
                } else {
                    tp[0] = fa0.x + fb0.x;
                }
            }
        } else {
            #pragma unroll
            for (int it = 0; it < 8; ++it) {
                int el = 32 * w + 4 * it + g;
                if (el < valid) {
                    uint2 A = Ps2[(size_t)sx[it] * 8 + j];
                    uint2 B = Pd2[(size_t)dx[it] * 8 + j];
                    const __half2* ah = reinterpret_cast<const __half2*>(&A);
                    const __half2* bh = reinterpret_cast<const __half2*>(&B);
                    float2 fa0 = __half22float2(ah[0]), fb0 = __half22float2(bh[0]);
                    float* tp = &tile[el * NC + c0];
                    if (c0 < 20) {
                        float2 fa1 = __half22float2(ah[1]), fb1 = __half22float2(bh[1]);
                        tp[0] = fa0.x + fb0.x; tp[1] = fa0.y + fb0.y;
                        tp[2] = fa1.x + fb1.x; tp[3] = fa1.y + fb1.y;
                    } else {
                        tp[0] = fa0.x + fb0.x;
                    }
                }
            }
        }
    }
    __syncthreads();

    float* outp = out + base * NC;
    if (valid == EPB) {
        // 1344 float4 = 5*EPB + 64: compile-time unrolled
        float4* o4 = reinterpret_cast<float4*>(outp);
        const float4* t4 = reinterpret_cast<const float4*>(tile);
        #pragma unroll
        for (int it = 0; it < 5; ++it)
            o4[tid + it * EPB] = t4[tid + it * EPB];
        if (tid < 64)
            o4[tid + 5 * EPB] = t4[tid + 5 * EPB];
    } else {
        const int total = valid * NC;
        for (int i = tid; i < total; i += EPB)
            outp[i] = tile[i];
    }
}

// ---------------------------------------------------------------------------
extern "C" void kernel_launch(void* const* d_in, const int* in_sizes, int n_in,
                              void* d_out, int out_size)
{
    const float* emb   = (const float*)d_in[0];
    const int*   ei    = (const int*)  d_in[1];
    const float* Wsrc  = (const float*)d_in[2];
    const float* Wdst  = (const float*)d_in[3];
    const float* bfuse = (const float*)d_in[4];
    const float* Wcls  = (const float*)d_in[5];
    const float* bcls  = (const float*)d_in[6];
    float* out = (float*)d_out;

    int N = in_sizes[0] / D;
    if (N > MAXN) N = MAXN;
    int E = in_sizes[1] / 2;

    const int prep_threads = 8 * (2 * D * NC + NC);
    prep_kernel<<<(prep_threads + 255) / 256, 256>>>(Wsrc, Wdst, bfuse, Wcls, bcls);

    // PDL: let project overlap prep's tail, edge overlap project's tail.
    cudaLaunchAttribute at[1];
    at[0].id = cudaLaunchAttributeProgrammaticStreamSerialization;
    at[0].val.programmaticStreamSerializationAllowed = 1;

    {
        cudaLaunchConfig_t cfg = {};
        cfg.gridDim  = dim3((unsigned)((N + 127) / 128), 1, 1);
        cfg.blockDim = dim3(128, 1, 1);
        cfg.dynamicSmemBytes = 0;
        cfg.stream = 0;
        cfg.attrs = at;
        cfg.numAttrs = 1;
        cudaLaunchKernelEx(&cfg, project_kernel, emb, N);
    }
    {
        cudaLaunchConfig_t cfg = {};
        cfg.gridDim  = dim3((unsigned)((E + EPB - 1) / EPB), 1, 1);
        cfg.blockDim = dim3(EPB, 1, 1);
        cfg.dynamicSmemBytes = 0;
        cfg.stream = 0;
        cfg.attrs = at;
        cfg.numAttrs = 1;
        cudaLaunchKernelEx(&cfg, edge_kernel, ei, out, E);
    }
}